// round 1
// baseline (speedup 1.0000x reference)
#include <cuda_runtime.h>
#include <cuda_bf16.h>

// -------- constants from the reference --------
#define POOL_SIZE   32
#define PROMPT_LEN  32
#define NCTX        32
#define EMBED       768
#define TOP_K       5
#define N_CLS       1000
#define SUFFIX_LEN  12
#define EMBED_F4    (EMBED / 4)          // 192
#define ROW_TOTAL   (1 + PROMPT_LEN + NCTX + SUFFIX_LEN)   // 77
#define CLS_F4      (ROW_TOTAL * EMBED_F4)                  // 14784
#define PROMPTS_F4  ((unsigned)N_CLS * CLS_F4)              // 14,784,000
#define POOL_F4     (POOL_SIZE * PROMPT_LEN * EMBED_F4)     // 196,608
#define KEY_F4      (POOL_SIZE * EMBED_F4)                  // 6,144

// -------- device scratch (no allocations allowed) --------
__device__ int   g_topidx[TOP_K];
__device__ float g_combined[PROMPT_LEN * EMBED];

// ============================================================
// Kernel A: query mean, cosine sims, top-5 selection (1 block)
// ============================================================
__global__ void kA_select(const float* __restrict__ x_embed,
                          const float* __restrict__ prompt_key)
{
    __shared__ float qs[EMBED];
    __shared__ float sim[POOL_SIZE];
    const int t = threadIdx.x;          // 256 threads
    const int warp = t >> 5, lane = t & 31;

    // q = sum over 16 frames (mean scale & q-norm don't affect ordering)
    for (int d = t; d < EMBED; d += 256) {
        float s = 0.f;
        #pragma unroll
        for (int i = 0; i < 16; ++i) s += x_embed[i * EMBED + d];
        qs[d] = s;
    }
    __syncthreads();

    // sim_p = (key_p . q) / ||key_p||  (order-equivalent to cosine sim)
    for (int p = warp; p < POOL_SIZE; p += 8) {
        const float* kp = prompt_key + p * EMBED;
        float dot = 0.f, nrm = 0.f;
        for (int d = lane; d < EMBED; d += 32) {
            float kv = kp[d];
            dot += kv * qs[d];
            nrm += kv * kv;
        }
        #pragma unroll
        for (int o = 16; o; o >>= 1) {
            dot += __shfl_down_sync(0xffffffffu, dot, o);
            nrm += __shfl_down_sync(0xffffffffu, nrm, o);
        }
        if (lane == 0) sim[p] = dot * rsqrtf(nrm);
    }
    __syncthreads();

    // top-5, strict '>' keeps lowest index on ties (matches jax.lax.top_k)
    if (t == 0) {
        bool used[POOL_SIZE];
        #pragma unroll
        for (int p = 0; p < POOL_SIZE; ++p) used[p] = false;
        for (int k = 0; k < TOP_K; ++k) {
            int best = 0; float bv = -3.0e38f;
            for (int p = 0; p < POOL_SIZE; ++p)
                if (!used[p] && sim[p] > bv) { bv = sim[p]; best = p; }
            used[best] = true;
            g_topidx[k] = best;
        }
    }
}

// ============================================================
// Kernel B: sigmoid gates + weighted sum -> combined[32,768]
// One block per token position l. 256 threads.
// ============================================================
__global__ void kB_combine(const float* __restrict__ prompt_pool,
                           const float* __restrict__ alpha_w,
                           const float* __restrict__ alpha_b)
{
    const int l = blockIdx.x;
    const int t = threadIdx.x, warp = t >> 5, lane = t & 31;
    __shared__ float wsh[TOP_K];
    __shared__ int   idxs[TOP_K];

    if (t < TOP_K) idxs[t] = g_topidx[t];
    __syncthreads();

    if (warp < TOP_K) {
        const float* row = prompt_pool + ((size_t)idxs[warp] * PROMPT_LEN + l) * EMBED;
        float dot = 0.f;
        for (int d = lane; d < EMBED; d += 32) dot += row[d] * alpha_w[d];
        #pragma unroll
        for (int o = 16; o; o >>= 1) dot += __shfl_down_sync(0xffffffffu, dot, o);
        if (lane == 0) wsh[warp] = 1.f / (1.f + __expf(-(dot + alpha_b[0])));
    }
    __syncthreads();

    const float w0 = wsh[0], w1 = wsh[1], w2 = wsh[2], w3 = wsh[3], w4 = wsh[4];
    const float* r0 = prompt_pool + ((size_t)idxs[0] * PROMPT_LEN + l) * EMBED;
    const float* r1 = prompt_pool + ((size_t)idxs[1] * PROMPT_LEN + l) * EMBED;
    const float* r2 = prompt_pool + ((size_t)idxs[2] * PROMPT_LEN + l) * EMBED;
    const float* r3 = prompt_pool + ((size_t)idxs[3] * PROMPT_LEN + l) * EMBED;
    const float* r4 = prompt_pool + ((size_t)idxs[4] * PROMPT_LEN + l) * EMBED;
    for (int d = t; d < EMBED; d += 256) {
        g_combined[l * EMBED + d] =
            w0 * r0[d] + w1 * r1[d] + w2 * r2[d] + w3 * r3[d] + w4 * r4[d];
    }
}

// ============================================================
// Kernel C: the bandwidth kernel — build prompts + copy pool/key.
// Flat float4 grid-stride. 32-bit indexing (total < 2^31).
// ============================================================
__global__ void kC_emit(const float* __restrict__ token_prefix,
                        const float* __restrict__ token_suffix,
                        const float* __restrict__ ctx,
                        const float* __restrict__ prompt_pool,
                        const float* __restrict__ prompt_key,
                        float4* __restrict__ out,
                        unsigned total_f4)
{
    const float4* __restrict__ pre4 = (const float4*)token_prefix;
    const float4* __restrict__ suf4 = (const float4*)token_suffix;
    const float4* __restrict__ ctx4 = (const float4*)ctx;
    const float4* __restrict__ cmb4 = (const float4*)g_combined;
    const float4* __restrict__ pol4 = (const float4*)prompt_pool;
    const float4* __restrict__ key4 = (const float4*)prompt_key;

    unsigned idx    = blockIdx.x * blockDim.x + threadIdx.x;
    const unsigned stride = gridDim.x * blockDim.x;

    for (; idx < total_f4; idx += stride) {
        float4 v;
        if (idx < PROMPTS_F4) {
            unsigned c   = idx / CLS_F4;              // magic-multiply, const divisor
            unsigned fc  = idx - c * CLS_F4;
            unsigned row = fc / EMBED_F4;
            unsigned col = fc - row * EMBED_F4;
            if (row == 0)
                v = pre4[c * EMBED_F4 + col];
            else if (row <= PROMPT_LEN)
                v = cmb4[(row - 1) * EMBED_F4 + col];
            else if (row <= PROMPT_LEN + NCTX)
                v = ctx4[(row - 1 - PROMPT_LEN) * EMBED_F4 + col];
            else
                v = suf4[c * (SUFFIX_LEN * EMBED_F4)
                         + (row - 1 - PROMPT_LEN - NCTX) * EMBED_F4 + col];
        } else {
            unsigned r = idx - PROMPTS_F4;
            v = (r < POOL_F4) ? pol4[r] : key4[r - POOL_F4];
        }
        out[idx] = v;
    }
}

// ============================================================
extern "C" void kernel_launch(void* const* d_in, const int* in_sizes, int n_in,
                              void* d_out, int out_size)
{
    const float* x_embed      = (const float*)d_in[0];
    const float* prompt_pool  = (const float*)d_in[1];
    const float* prompt_key   = (const float*)d_in[2];
    const float* alpha_w      = (const float*)d_in[3];
    const float* alpha_b      = (const float*)d_in[4];
    const float* ctx          = (const float*)d_in[5];
    const float* token_prefix = (const float*)d_in[6];
    const float* token_suffix = (const float*)d_in[7];
    // d_in[8] = train_flag: penalty is a positive scalar on sims -> ordering
    // (and therefore the output) is unchanged; safely ignored.

    kA_select<<<1, 256>>>(x_embed, prompt_key);
    kB_combine<<<PROMPT_LEN, 256>>>(prompt_pool, alpha_w, alpha_b);

    const unsigned total_f4 = (unsigned)(out_size / 4);
    const int threads = 256;
    unsigned want = (total_f4 + 7u) / 8u;                 // ~8 f4 per thread
    unsigned blocks = (want + threads - 1) / threads;
    if (blocks > 16384u) blocks = 16384u;
    if (blocks < 1u) blocks = 1u;
    kC_emit<<<blocks, threads>>>(token_prefix, token_suffix, ctx,
                                 prompt_pool, prompt_key,
                                 (float4*)d_out, total_f4);
}